// round 8
// baseline (speedup 1.0000x reference)
#include <cuda_runtime.h>
#include <math.h>

// Problem constants (fixed by the dataset)
#define VOCAB   32000
#define NBL     128        // B*L
#define NK      64         // 8 heads x 8

// Main-kernel tiling: 256 threads, each owns 4 bl-rows x 8 vocab-cols
#define BM      128        // full bl dimension per CTA
#define BN      64         // vocab tile -> grid.x = 500 (single wave @ occ 4)
#define KC      8          // k chunk for bl-coefficient smem (12KB)
#define NTHR    256

typedef unsigned long long u64;

// ---------------------------------------------------------------------------
// Packed f32x2 helpers
// ---------------------------------------------------------------------------
__device__ __forceinline__ u64 pk(float x, float y) {
    u64 r; asm("mov.b64 %0, {%1, %2};" : "=l"(r) : "f"(x), "f"(y)); return r;
}
__device__ __forceinline__ void upk(u64 a, float& x, float& y) {
    asm("mov.b64 {%0, %1}, %2;" : "=f"(x), "=f"(y) : "l"(a));
}
__device__ __forceinline__ u64 mul2(u64 a, u64 b) {
    u64 r; asm("mul.rn.f32x2 %0, %1, %2;" : "=l"(r) : "l"(a), "l"(b)); return r;
}
__device__ __forceinline__ u64 fma2(u64 a, u64 b, u64 c) {
    u64 r; asm("fma.rn.f32x2 %0, %1, %2, %3;" : "=l"(r) : "l"(a), "l"(b), "l"(c)); return r;
}

// ---------------------------------------------------------------------------
// Device scratch: per-(k,bl) scalar coefficient planes
// ---------------------------------------------------------------------------
__device__ __align__(16) float g_cp[NK * NBL];   // [k][bl] = W[h]*a*cos(p - iph)
__device__ __align__(16) float g_ep[NK * NBL];   // [k][bl] = e^freq
__device__ __align__(16) float g_em[NK * NBL];   // [k][bl] = e^-freq

__global__ void prep_bl(const float* __restrict__ freqs,
                        const float* __restrict__ amps,
                        const float* __restrict__ phases,
                        const float* __restrict__ iph,
                        const float* __restrict__ W) {
    int idx = blockIdx.x * 256 + threadIdx.x;   // idx = bl*NK + k
    int bl = idx >> 6, k = idx & 63;
    float cp = amps[idx] * cosf(phases[idx] - iph[k]) * W[k >> 3];
    float f  = freqs[idx];
    int o = k * NBL + bl;
    g_cp[o] = cp;
    g_ep[o] = expf(f);
    g_em[o] = expf(-f);
}

// ---------------------------------------------------------------------------
// Main: out[bl][v] = sum_k cp * min(e^f * e^-vp, e^-f * e^vp) + bias
//  - vocab smem: [k][pair p] float4 = (em_2p, em_2p+1, ep_2p, ep_2p+1)
//    thread c reads pairs {c, c+8, c+16, c+24}: conflict-free LDS.128
//  - bl smem: 3 scalar planes [KC][BM]; one broadcast LDS.128 per plane/kl
//  - 64 regs/thread -> 4 CTAs/SM (32 warps), grid 500 = single wave
// ---------------------------------------------------------------------------
__global__ void __launch_bounds__(NTHR, 4)
main_kernel(float* __restrict__ out,
            const float* __restrict__ vp,
            const float* __restrict__ bptr) {
    extern __shared__ char sm[];
    float4* s_v  = (float4*)sm;                   // [NK][32] pairs   32KB
    float*  s_cp = (float*)(sm + NK * 32 * 16);   // [KC][BM]          4KB
    float*  s_ep = s_cp + KC * BM;                //                   4KB
    float*  s_em = s_ep + KC * BM;                //                   4KB

    const int tid   = threadIdx.x;
    const int vbase = blockIdx.x * BN;

    // --- In-kernel vocab exp fill: 2048 (pair,k) items, 8 per thread ---
    #pragma unroll
    for (int it = 0; it < 8; ++it) {
        int idx = it * NTHR + tid;          // lanes sweep k -> coalesced LDG
        int p = idx >> 6;                   // 0..31
        int k = idx & 63;
        long a = (long)(vbase + 2 * p) * NK + k;
        float x0 = vp[a];
        float x1 = vp[a + NK];
        s_v[k * 32 + p] = make_float4(__expf(-x0), __expf(-x1),
                                      __expf(x0),  __expf(x1));
    }

    const int c  = tid & 7;                 // vocab pair group
    const int r4 = tid >> 3;                // bl row-group (float4 index)

    const float bias = bptr[0];
    const u64 bias2 = pk(bias, bias);
    u64 acc[4][4];
    #pragma unroll
    for (int i = 0; i < 4; ++i)
        #pragma unroll
        for (int j = 0; j < 4; ++j) acc[i][j] = bias2;   // bias folded into init

    for (int kc = 0; kc < NK; kc += KC) {
        // --- bl chunk fill: 3 planes x 256 float4, coalesced (1 iter) ---
        const float4* gc = (const float4*)(g_cp + kc * NBL);
        const float4* ge = (const float4*)(g_ep + kc * NBL);
        const float4* gm = (const float4*)(g_em + kc * NBL);
        {
            int idx = tid;                              // 256 float4 per plane
            ((float4*)s_cp)[idx] = gc[idx];
            ((float4*)s_ep)[idx] = ge[idx];
            ((float4*)s_em)[idx] = gm[idx];
        }
        __syncthreads();   // also covers the vocab fill on the first chunk

        #pragma unroll
        for (int kl = 0; kl < KC; ++kl) {
            const ulonglong2* vv = (const ulonglong2*)s_v + (kc + kl) * 32 + c;
            ulonglong2 q0 = vv[0];     // .x=(em,em') .y=(ep,ep')
            ulonglong2 q1 = vv[8];
            ulonglong2 q2 = vv[16];
            ulonglong2 q3 = vv[24];

            // one broadcast LDS.128 per plane -> this thread's 4 rows
            float4 vc  = ((const float4*)(s_cp + kl * BM))[r4];
            float4 veq = ((const float4*)(s_ep + kl * BM))[r4];
            float4 vmq = ((const float4*)(s_em + kl * BM))[r4];
            const float* vcf = (const float*)&vc;
            const float* vef = (const float*)&veq;
            const float* vmf = (const float*)&vmq;

            #pragma unroll
            for (int i = 0; i < 4; ++i) {
                float cs = vcf[i], es = vef[i], ms = vmf[i];
                u64 cpd = pk(cs, cs);
                u64 epd = pk(es, es);
                u64 emd = pk(ms, ms);
                {
                    u64 t1 = mul2(epd, q0.x), t2 = mul2(emd, q0.y);
                    float a0, a1, b0, b1; upk(t1, a0, a1); upk(t2, b0, b1);
                    acc[i][0] = fma2(cpd, pk(fminf(a0, b0), fminf(a1, b1)), acc[i][0]);
                }
                {
                    u64 t1 = mul2(epd, q1.x), t2 = mul2(emd, q1.y);
                    float a0, a1, b0, b1; upk(t1, a0, a1); upk(t2, b0, b1);
                    acc[i][1] = fma2(cpd, pk(fminf(a0, b0), fminf(a1, b1)), acc[i][1]);
                }
                {
                    u64 t1 = mul2(epd, q2.x), t2 = mul2(emd, q2.y);
                    float a0, a1, b0, b1; upk(t1, a0, a1); upk(t2, b0, b1);
                    acc[i][2] = fma2(cpd, pk(fminf(a0, b0), fminf(a1, b1)), acc[i][2]);
                }
                {
                    u64 t1 = mul2(epd, q3.x), t2 = mul2(emd, q3.y);
                    float a0, a1, b0, b1; upk(t1, a0, a1); upk(t2, b0, b1);
                    acc[i][3] = fma2(cpd, pk(fminf(a0, b0), fminf(a1, b1)), acc[i][3]);
                }
            }
        }
        __syncthreads();
    }

    // --- Epilogue: 4 rows x 4 u64 pair-stores each (bias already in acc) ---
    #pragma unroll
    for (int i = 0; i < 4; ++i) {
        long rowbase = (long)(4 * r4 + i) * VOCAB + vbase + 2 * c;
        #pragma unroll
        for (int j = 0; j < 4; ++j) {
            *(u64*)&out[rowbase + 16 * j] = acc[i][j];
        }
    }
}

// ---------------------------------------------------------------------------
extern "C" void kernel_launch(void* const* d_in, const int* in_sizes, int n_in,
                              void* d_out, int out_size) {
    const float* freqs  = (const float*)d_in[0];
    const float* amps   = (const float*)d_in[1];
    const float* phases = (const float*)d_in[2];
    const float* vp     = (const float*)d_in[3];
    const float* iph    = (const float*)d_in[4];
    const float* W      = (const float*)d_in[5];
    const float* b      = (const float*)d_in[6];
    float* out = (float*)d_out;

    prep_bl<<<(NBL * NK) / 256, 256>>>(freqs, amps, phases, iph, W);

    const int smem_bytes = NK * 32 * 16 + 3 * KC * BM * (int)sizeof(float);  // 45056
    cudaFuncSetAttribute(main_kernel, cudaFuncAttributeMaxDynamicSharedMemorySize, smem_bytes);
    cudaFuncSetAttribute(main_kernel, cudaFuncAttributePreferredSharedMemoryCarveout, 100);

    main_kernel<<<VOCAB / BN, NTHR, smem_bytes>>>(out, vp, b);
    (void)in_sizes; (void)n_in; (void)out_size;
}

// round 10
// speedup vs baseline: 1.4018x; 1.4018x over previous
#include <cuda_runtime.h>
#include <math.h>

// Problem constants (fixed by the dataset)
#define VOCAB   32000
#define NBL     128        // B*L
#define NK      64         // 8 heads x 8

// Main-kernel tiling: 256 threads, each owns 4 bl-rows x 8 vocab-cols
#define BM      128        // full bl dimension per CTA
#define BN      64         // vocab tile -> grid.x = 500
#define KC      8          // k chunk for bl-coefficient smem
#define NTHR    256

typedef unsigned long long u64;

// ---------------------------------------------------------------------------
// Packed f32x2 helpers
// ---------------------------------------------------------------------------
__device__ __forceinline__ u64 pk(float x, float y) {
    u64 r; asm("mov.b64 %0, {%1, %2};" : "=l"(r) : "f"(x), "f"(y)); return r;
}
__device__ __forceinline__ void upk(u64 a, float& x, float& y) {
    asm("mov.b64 {%0, %1}, %2;" : "=f"(x), "=f"(y) : "l"(a));
}
__device__ __forceinline__ u64 mul2(u64 a, u64 b) {
    u64 r; asm("mul.rn.f32x2 %0, %1, %2;" : "=l"(r) : "l"(a), "l"(b)); return r;
}
__device__ __forceinline__ u64 fma2(u64 a, u64 b, u64 c) {
    u64 r; asm("fma.rn.f32x2 %0, %1, %2, %3;" : "=l"(r) : "l"(a), "l"(b), "l"(c)); return r;
}
// Packed min emulated with two scalar FMNMX on the register halves
// (upk/pk are register-aliasing MOVs that ptxas largely folds away)
__device__ __forceinline__ u64 minp(u64 a, u64 b) {
    float a0, a1, b0, b1;
    upk(a, a0, a1); upk(b, b0, b1);
    return pk(fminf(a0, b0), fminf(a1, b1));
}

// ---------------------------------------------------------------------------
// Device scratch: per-(k,bl) coefficient planes (2 planes after factoring)
//   g_ce[k][bl] = cp * e^f          (cp = W[h]*a*cos(p - iph))
//   g_e2[k][bl] = e^{-2f}
// ---------------------------------------------------------------------------
__device__ __align__(16) float g_ce[NK * NBL];
__device__ __align__(16) float g_e2[NK * NBL];

__global__ void prep_bl(const float* __restrict__ freqs,
                        const float* __restrict__ amps,
                        const float* __restrict__ phases,
                        const float* __restrict__ iph,
                        const float* __restrict__ W) {
    int idx = blockIdx.x * 256 + threadIdx.x;   // idx = bl*NK + k
    int bl = idx >> 6, k = idx & 63;
    float cp = amps[idx] * cosf(phases[idx] - iph[k]) * W[k >> 3];
    float f  = freqs[idx];
    int o = k * NBL + bl;
    g_ce[o] = cp * expf(f);
    g_e2[o] = expf(-2.0f * f);
}

// ---------------------------------------------------------------------------
// Main: out[bl][v] = sum_k (cp*e^f) * min(e^-vp, e^-2f * e^vp) + bias
//  - vocab smem: [k][pair p] float4 = (em_2p, em_2p+1, ep_2p, ep_2p+1)
//    thread c reads pairs {c, c+8, c+16, c+24}: conflict-free LDS.128
//  - bl smem: 2 scalar planes [KC][BM]; one broadcast LDS.128 per plane/kl
//  - packed core: MUL2, FMNMX, FMNMX, FMA2 per 2 output elements
// ---------------------------------------------------------------------------
__global__ void __launch_bounds__(NTHR, 3)
main_kernel(float* __restrict__ out,
            const float* __restrict__ vp,
            const float* __restrict__ bptr) {
    extern __shared__ char sm[];
    float4* s_v  = (float4*)sm;                   // [NK][32] pairs   32KB
    float*  s_ce = (float*)(sm + NK * 32 * 16);   // [KC][BM]          4KB
    float*  s_e2 = s_ce + KC * BM;                //                   4KB

    const int tid   = threadIdx.x;
    const int vbase = blockIdx.x * BN;

    // --- In-kernel vocab exp fill: 2048 (pair,k) items, 8 per thread ---
    #pragma unroll
    for (int it = 0; it < 8; ++it) {
        int idx = it * NTHR + tid;          // lanes sweep k -> coalesced LDG
        int p = idx >> 6;                   // 0..31
        int k = idx & 63;
        long a = (long)(vbase + 2 * p) * NK + k;
        float x0 = vp[a];
        float x1 = vp[a + NK];
        s_v[k * 32 + p] = make_float4(__expf(-x0), __expf(-x1),
                                      __expf(x0),  __expf(x1));
    }

    const int c  = tid & 7;                 // vocab pair group
    const int r4 = tid >> 3;                // bl row-group (float4 index)

    const float bias = bptr[0];
    const u64 bias2 = pk(bias, bias);
    u64 acc[4][4];
    #pragma unroll
    for (int i = 0; i < 4; ++i)
        #pragma unroll
        for (int j = 0; j < 4; ++j) acc[i][j] = bias2;   // bias folded into init

    for (int kc = 0; kc < NK; kc += KC) {
        // --- bl chunk fill: 2 planes x 256 float4, coalesced (1 iter) ---
        const float4* gc = (const float4*)(g_ce + kc * NBL);
        const float4* ge = (const float4*)(g_e2 + kc * NBL);
        {
            int idx = tid;                              // 256 float4 per plane
            ((float4*)s_ce)[idx] = gc[idx];
            ((float4*)s_e2)[idx] = ge[idx];
        }
        __syncthreads();   // also covers the vocab fill on the first chunk

        #pragma unroll
        for (int kl = 0; kl < KC; ++kl) {
            const ulonglong2* vv = (const ulonglong2*)s_v + (kc + kl) * 32 + c;
            ulonglong2 q0 = vv[0];     // .x=(em,em') .y=(ep,ep')
            ulonglong2 q1 = vv[8];
            ulonglong2 q2 = vv[16];
            ulonglong2 q3 = vv[24];

            // one broadcast LDS.128 per plane -> this thread's 4 rows
            float4 vc = ((const float4*)(s_ce + kl * BM))[r4];
            float4 v2 = ((const float4*)(s_e2 + kl * BM))[r4];
            const float* vcf = (const float*)&vc;
            const float* v2f = (const float*)&v2;

            #pragma unroll
            for (int i = 0; i < 4; ++i) {
                u64 ced = pk(vcf[i], vcf[i]);
                u64 e2d = pk(v2f[i], v2f[i]);

                acc[i][0] = fma2(ced, minp(q0.x, mul2(e2d, q0.y)), acc[i][0]);
                acc[i][1] = fma2(ced, minp(q1.x, mul2(e2d, q1.y)), acc[i][1]);
                acc[i][2] = fma2(ced, minp(q2.x, mul2(e2d, q2.y)), acc[i][2]);
                acc[i][3] = fma2(ced, minp(q3.x, mul2(e2d, q3.y)), acc[i][3]);
            }
        }
        __syncthreads();
    }

    // --- Epilogue: 4 rows x 4 u64 pair-stores each (bias already in acc) ---
    #pragma unroll
    for (int i = 0; i < 4; ++i) {
        long rowbase = (long)(4 * r4 + i) * VOCAB + vbase + 2 * c;
        #pragma unroll
        for (int j = 0; j < 4; ++j) {
            *(u64*)&out[rowbase + 16 * j] = acc[i][j];
        }
    }
}

// ---------------------------------------------------------------------------
extern "C" void kernel_launch(void* const* d_in, const int* in_sizes, int n_in,
                              void* d_out, int out_size) {
    const float* freqs  = (const float*)d_in[0];
    const float* amps   = (const float*)d_in[1];
    const float* phases = (const float*)d_in[2];
    const float* vp     = (const float*)d_in[3];
    const float* iph    = (const float*)d_in[4];
    const float* W      = (const float*)d_in[5];
    const float* b      = (const float*)d_in[6];
    float* out = (float*)d_out;

    prep_bl<<<(NBL * NK) / 256, 256>>>(freqs, amps, phases, iph, W);

    const int smem_bytes = NK * 32 * 16 + 2 * KC * BM * (int)sizeof(float);  // 36864
    cudaFuncSetAttribute(main_kernel, cudaFuncAttributeMaxDynamicSharedMemorySize, smem_bytes);
    cudaFuncSetAttribute(main_kernel, cudaFuncAttributePreferredSharedMemoryCarveout, 100);

    main_kernel<<<VOCAB / BN, NTHR, smem_bytes>>>(out, vp, b);
    (void)in_sizes; (void)n_in; (void)out_size;
}

// round 11
// speedup vs baseline: 1.4796x; 1.0555x over previous
#include <cuda_runtime.h>
#include <math.h>

// Problem constants (fixed by the dataset)
#define VOCAB   32000
#define NBL     128        // B*L
#define NK      64         // 8 heads x 8

// Main-kernel tiling: 128 threads, each owns 8 bl-rows x 8 vocab-cols
#define BM      128        // full bl dimension per CTA
#define BN      64         // vocab tile -> grid.x = 500
#define KC      8          // k chunk for bl-coefficient smem
#define NTHR    128

typedef unsigned long long u64;

// ---------------------------------------------------------------------------
// Packed f32x2 helpers
// ---------------------------------------------------------------------------
__device__ __forceinline__ u64 pk(float x, float y) {
    u64 r; asm("mov.b64 %0, {%1, %2};" : "=l"(r) : "f"(x), "f"(y)); return r;
}
__device__ __forceinline__ void upk(u64 a, float& x, float& y) {
    asm("mov.b64 {%0, %1}, %2;" : "=f"(x), "=f"(y) : "l"(a));
}
__device__ __forceinline__ u64 mul2(u64 a, u64 b) {
    u64 r; asm("mul.rn.f32x2 %0, %1, %2;" : "=l"(r) : "l"(a), "l"(b)); return r;
}
__device__ __forceinline__ u64 fma2(u64 a, u64 b, u64 c) {
    u64 r; asm("fma.rn.f32x2 %0, %1, %2, %3;" : "=l"(r) : "l"(a), "l"(b), "l"(c)); return r;
}
// Packed min via two scalar FMNMX on register halves (pk/upk fold to aliases)
__device__ __forceinline__ u64 minp(u64 a, u64 b) {
    float a0, a1, b0, b1;
    upk(a, a0, a1); upk(b, b0, b1);
    return pk(fminf(a0, b0), fminf(a1, b1));
}

// ---------------------------------------------------------------------------
// Device scratch: 2 factored coefficient planes
//   g_ce[k][bl] = cp * e^f       (cp = W[h]*a*cos(p - iph))
//   g_e2[k][bl] = e^{-2f}
// ---------------------------------------------------------------------------
__device__ __align__(16) float g_ce[NK * NBL];
__device__ __align__(16) float g_e2[NK * NBL];

__global__ void prep_bl(const float* __restrict__ freqs,
                        const float* __restrict__ amps,
                        const float* __restrict__ phases,
                        const float* __restrict__ iph,
                        const float* __restrict__ W) {
    int idx = blockIdx.x * 256 + threadIdx.x;   // idx = bl*NK + k
    int bl = idx >> 6, k = idx & 63;
    float cp = amps[idx] * cosf(phases[idx] - iph[k]) * W[k >> 3];
    float f  = freqs[idx];
    int o = k * NBL + bl;
    g_ce[o] = cp * expf(f);
    g_e2[o] = expf(-2.0f * f);
}

// ---------------------------------------------------------------------------
// Main: out[bl][v] = sum_k (cp*e^f) * min(e^-vp, e^-2f * e^vp) + bias
//  - vocab smem: [k][pair p] float4 = (em_2p, em_2p+1, ep_2p, ep_2p+1)
//    thread c reads pairs {c, c+8, c+16, c+24}: conflict-free LDS.128,
//    each vocab load now amortized over 8 bl rows (TM=8)
//  - bl smem: 2 scalar planes [KC][BM]; two LDS.128 per plane per kl
// ---------------------------------------------------------------------------
__global__ void __launch_bounds__(NTHR, 4)
main_kernel(float* __restrict__ out,
            const float* __restrict__ vp,
            const float* __restrict__ bptr) {
    extern __shared__ char sm[];
    float4* s_v  = (float4*)sm;                   // [NK][32] pairs   32KB
    float*  s_ce = (float*)(sm + NK * 32 * 16);   // [KC][BM]          4KB
    float*  s_e2 = s_ce + KC * BM;                //                   4KB

    const int tid   = threadIdx.x;
    const int vbase = blockIdx.x * BN;

    // --- In-kernel vocab exp fill: 2048 (pair,k) items, 16 per thread ---
    #pragma unroll
    for (int it = 0; it < 16; ++it) {
        int idx = it * NTHR + tid;          // lanes sweep k -> coalesced LDG
        int p = idx >> 6;                   // 0..31
        int k = idx & 63;
        long a = (long)(vbase + 2 * p) * NK + k;
        float x0 = vp[a];
        float x1 = vp[a + NK];
        s_v[k * 32 + p] = make_float4(__expf(-x0), __expf(-x1),
                                      __expf(x0),  __expf(x1));
    }

    const int c  = tid & 7;                 // vocab pair group
    const int rg = tid >> 3;                // bl row-group: rows 8*rg..8*rg+7

    const float bias = bptr[0];
    const u64 bias2 = pk(bias, bias);
    u64 acc[8][4];
    #pragma unroll
    for (int i = 0; i < 8; ++i)
        #pragma unroll
        for (int j = 0; j < 4; ++j) acc[i][j] = bias2;   // bias folded into init

    for (int kc = 0; kc < NK; kc += KC) {
        // --- bl chunk fill: 2 planes x 256 float4, coalesced (2 iters) ---
        const float4* gc = (const float4*)(g_ce + kc * NBL);
        const float4* ge = (const float4*)(g_e2 + kc * NBL);
        #pragma unroll
        for (int it = 0; it < (KC * BM / 4) / NTHR; ++it) {
            int idx = it * NTHR + tid;
            ((float4*)s_ce)[idx] = gc[idx];
            ((float4*)s_e2)[idx] = ge[idx];
        }
        __syncthreads();   // also covers the vocab fill on the first chunk

        #pragma unroll
        for (int kl = 0; kl < KC; ++kl) {
            const ulonglong2* vv = (const ulonglong2*)s_v + (kc + kl) * 32 + c;
            ulonglong2 q0 = vv[0];     // .x=(em,em') .y=(ep,ep')
            ulonglong2 q1 = vv[8];
            ulonglong2 q2 = vv[16];
            ulonglong2 q3 = vv[24];

            // this thread's 8 rows: 2 LDS.128 per plane
            const float4* pce = (const float4*)(s_ce + kl * BM) + 2 * rg;
            const float4* pe2 = (const float4*)(s_e2 + kl * BM) + 2 * rg;
            float4 vc0 = pce[0], vc1 = pce[1];
            float4 v20 = pe2[0], v21 = pe2[1];
            const float* vcf = (const float*)&vc0;   // [0..7] contiguous pair
            const float* v2f = (const float*)&v20;
            (void)vc1; (void)v21;                    // vc1/v21 alias vcf[4..7]

            #pragma unroll
            for (int i = 0; i < 8; ++i) {
                float cs = (i < 4) ? ((const float*)&vc0)[i] : ((const float*)&vc1)[i - 4];
                float es = (i < 4) ? ((const float*)&v20)[i] : ((const float*)&v21)[i - 4];
                u64 ced = pk(cs, cs);
                u64 e2d = pk(es, es);

                acc[i][0] = fma2(ced, minp(q0.x, mul2(e2d, q0.y)), acc[i][0]);
                acc[i][1] = fma2(ced, minp(q1.x, mul2(e2d, q1.y)), acc[i][1]);
                acc[i][2] = fma2(ced, minp(q2.x, mul2(e2d, q2.y)), acc[i][2]);
                acc[i][3] = fma2(ced, minp(q3.x, mul2(e2d, q3.y)), acc[i][3]);
            }
            (void)vcf; (void)v2f;
        }
        __syncthreads();
    }

    // --- Epilogue: 8 rows x 4 u64 pair-stores each (bias already in acc) ---
    #pragma unroll
    for (int i = 0; i < 8; ++i) {
        long rowbase = (long)(8 * rg + i) * VOCAB + vbase + 2 * c;
        #pragma unroll
        for (int j = 0; j < 4; ++j) {
            *(u64*)&out[rowbase + 16 * j] = acc[i][j];
        }
    }
}

// ---------------------------------------------------------------------------
extern "C" void kernel_launch(void* const* d_in, const int* in_sizes, int n_in,
                              void* d_out, int out_size) {
    const float* freqs  = (const float*)d_in[0];
    const float* amps   = (const float*)d_in[1];
    const float* phases = (const float*)d_in[2];
    const float* vp     = (const float*)d_in[3];
    const float* iph    = (const float*)d_in[4];
    const float* W      = (const float*)d_in[5];
    const float* b      = (const float*)d_in[6];
    float* out = (float*)d_out;

    prep_bl<<<(NBL * NK) / 256, 256>>>(freqs, amps, phases, iph, W);

    const int smem_bytes = NK * 32 * 16 + 2 * KC * BM * (int)sizeof(float);  // 36864
    cudaFuncSetAttribute(main_kernel, cudaFuncAttributeMaxDynamicSharedMemorySize, smem_bytes);
    cudaFuncSetAttribute(main_kernel, cudaFuncAttributePreferredSharedMemoryCarveout, 100);

    main_kernel<<<VOCAB / BN, NTHR, smem_bytes>>>(out, vp, b);
    (void)in_sizes; (void)n_in; (void)out_size;
}